// round 12
// baseline (speedup 1.0000x reference)
#include <cuda_runtime.h>
#include <math.h>

// Problem constants
#define NN 512          // image size
#define NA 30           // angles
#define ND 729          // detectors
#define NL 3            // layers
#define NB 2            // batch
#define NC 32           // hidden channels

#define PI_F 3.14159265358979323846f

static const int BNN = NB * NN * NN;           // 524288
static const int BAD = NB * NA * ND;           // 43740
static const int NODD = 364;                   // number of odd taps 1..727

// ---------------- scratch (device globals; no allocation allowed) -----------
__device__ float g_X[NB * NN * NN];
__device__ float g_Z[NB * NN * NN];
__device__ float g_noise[NB * NN * NN];
__device__ float g_f0[NB * NC * NN * NN];
__device__ float g_f1[NB * NC * NN * NN];
__device__ float g_sp[NB * NA * ND];
__device__ float g_res[NB * NA * ND];

// ---------------- trivial copy ----------------------------------------------
__global__ void copy_kernel(float* __restrict__ dst, const float* __restrict__ src, int n) {
    int i = blockIdx.x * blockDim.x + threadIdx.x;
    if (i < n) dst[i] = src[i];
}

// ---------------- Radon forward ----------------------------------------------
// out[b,a,s] = sum_t bilinear(img_b, row = sv*sn + tv*cs + 255.5,
//                                     col = sv*cs - tv*sn + 255.5)
// One warp per output element, lanes stride over t.
__global__ void radon_kernel(const float* __restrict__ img,
                             const float* __restrict__ theta,
                             float* __restrict__ out) {
    int gw   = (int)((blockIdx.x * blockDim.x + threadIdx.x) >> 5);
    int lane = threadIdx.x & 31;
    if (gw >= BAD) return;
    int b   = gw / (NA * ND);
    int rem = gw - b * NA * ND;
    int a   = rem / ND;
    int s   = rem - a * ND;

    float th = theta[a];
    float cs = cosf(th), sn = sinf(th);
    float sv = (float)s - 364.0f;
    float base_r = sv * sn + 255.5f;
    float base_c = sv * cs + 255.5f;
    const float* im = img + b * NN * NN;

    float acc = 0.0f;
    for (int t = lane; t < ND; t += 32) {
        float tv = (float)t - 364.0f;
        float r = base_r + tv * cs;
        float c = base_c - tv * sn;
        float rf = floorf(r), cf = floorf(c);
        int r0 = (int)rf, c0 = (int)cf;
        float wr = r - rf, wc = c - cf;
        float v00 = 0.f, v01 = 0.f, v10 = 0.f, v11 = 0.f;
        bool r0k = (unsigned)r0 < (unsigned)NN;
        bool r1k = (unsigned)(r0 + 1) < (unsigned)NN;
        bool c0k = (unsigned)c0 < (unsigned)NN;
        bool c1k = (unsigned)(c0 + 1) < (unsigned)NN;
        if (r0k) {
            const float* rp = im + r0 * NN;
            if (c0k) v00 = rp[c0];
            if (c1k) v01 = rp[c0 + 1];
        }
        if (r1k) {
            const float* rp = im + (r0 + 1) * NN;
            if (c0k) v10 = rp[c0];
            if (c1k) v11 = rp[c0 + 1];
        }
        acc += (1.f - wr) * ((1.f - wc) * v00 + wc * v01)
             +        wr  * ((1.f - wc) * v10 + wc * v11);
    }
#pragma unroll
    for (int o = 16; o; o >>= 1) acc += __shfl_xor_sync(0xffffffffu, acc, o);
    if (lane == 0) out[gw] = acc;
}

// ---------------- Ramp filter (analytic time-domain equivalent) --------------
// g[m] = 0.5*sp[m] - (2/pi^2) * sum_{d odd} (sp[m-d] + sp[m+d]) / d^2
// filtered = g * pi/(2A)
// mode 0: out = sino - filtered        (data-consistency residual)
// mode 1: out = filtered
__global__ void filter_kernel(const float* __restrict__ sp,
                              const float* __restrict__ sino,
                              float* __restrict__ out, int mode) {
    __shared__ float row[ND];
    __shared__ float coef[NODD];
    int ba = blockIdx.x;                 // b*NA + a
    const float* r = sp + ba * ND;
    for (int i = threadIdx.x; i < ND; i += blockDim.x) row[i] = r[i];
    for (int i = threadIdx.x; i < NODD; i += blockDim.x) {
        float d = 2.0f * (float)i + 1.0f;
        coef[i] = -2.0f / (PI_F * PI_F * d * d);
    }
    __syncthreads();
    const float scale = PI_F / (2.0f * (float)NA);
    for (int m = threadIdx.x; m < ND; m += blockDim.x) {
        float g = 0.5f * row[m];
        for (int i = 0; i < NODD; i++) {
            int d = 2 * i + 1;
            float sum = 0.f;
            int lo = m - d; if (lo >= 0) sum += row[lo];
            int hi = m + d; if (hi < ND) sum += row[hi];
            g = fmaf(coef[i], sum, g);
        }
        float filtered = g * scale;
        out[ba * ND + m] = (mode == 0) ? (sino[ba * ND + m] - filtered) : filtered;
    }
}

// ---------------- Backprojection (fused epilogue) -----------------------------
// bp[b,i,j] = sum_a lerp(sino[b,a], cs*xj + sn*xi + 364)
// mode 0: out = base + step*bp                (z = X + step*outputs)
// mode 1: out = base + addl - step*bp         (X = z + noise - step*outputs_noise)
__global__ void backproj_kernel(const float* __restrict__ sino,
                                const float* __restrict__ theta,
                                const float* __restrict__ base,
                                const float* __restrict__ addl,
                                float* __restrict__ out,
                                const float* __restrict__ steps, int layer,
                                int mode) {
    __shared__ float cs_s[NA], sn_s[NA];
    if (threadIdx.x < NA) {
        float th = theta[threadIdx.x];
        cs_s[threadIdx.x] = cosf(th);
        sn_s[threadIdx.x] = sinf(th);
    }
    __syncthreads();
    int p = blockIdx.x * blockDim.x + threadIdx.x;
    if (p >= BNN) return;
    int b  = p / (NN * NN);
    int ij = p - b * NN * NN;
    int i  = ij / NN, j = ij - i * NN;
    float xi = (float)i - 255.5f;
    float xj = (float)j - 255.5f;
    const float* srow = sino + b * NA * ND;
    float acc = 0.0f;
#pragma unroll 5
    for (int a = 0; a < NA; a++) {
        float idx = cs_s[a] * xj + sn_s[a] * xi + 364.0f;
        float lof = floorf(idx);
        int lo = (int)lof;
        float w = idx - lof;
        float v = 0.f;
        if ((unsigned)lo < (unsigned)ND)       v += srow[a * ND + lo] * (1.0f - w);
        if ((unsigned)(lo + 1) < (unsigned)ND) v += srow[a * ND + lo + 1] * w;
        acc += v;
    }
    float step = steps[layer];
    float r;
    if (mode == 0) r = base[p] + step * acc;
    else           r = base[p] + addl[p] - step * acc;
    out[p] = r;
}

// ---------------- Conv 1 -> 32, ReLU -----------------------------------------
// grid (NN/32, NN/8, NB), block 256; one thread per pixel, 32 oc accumulators.
__global__ void conv1_kernel(const float* __restrict__ in,   // [B,N,N]
                             const float* __restrict__ w,    // [32,1,3,3]
                             const float* __restrict__ bias, // [32]
                             float* __restrict__ out) {      // [B,32,N,N]
    __shared__ float ws[32 * 9];
    __shared__ float bs[32];
    __shared__ float tile[10][35];
    int tid = threadIdx.x;
    for (int i = tid; i < 288; i += 256) ws[i] = w[i];   // FIXED: full 288 loads
    if (tid < 32)  bs[tid] = bias[tid];
    int tx0 = blockIdx.x * 32, ty0 = blockIdx.y * 8, b = blockIdx.z;
    const float* ip = in + b * NN * NN;
    for (int i = tid; i < 340; i += 256) {
        int r = i / 34, c = i % 34;
        int gy = ty0 + r - 1, gx = tx0 + c - 1;
        tile[r][c] = ((unsigned)gy < (unsigned)NN && (unsigned)gx < (unsigned)NN)
                         ? ip[gy * NN + gx] : 0.f;
    }
    __syncthreads();
    int lx = tid & 31, ly = tid >> 5;
    float p[9];
#pragma unroll
    for (int ky = 0; ky < 3; ky++)
#pragma unroll
        for (int kx = 0; kx < 3; kx++) p[ky * 3 + kx] = tile[ly + ky][lx + kx];
    int gy = ty0 + ly, gx = tx0 + lx;
#pragma unroll
    for (int oc = 0; oc < 32; oc++) {
        float acc = bs[oc];
#pragma unroll
        for (int k = 0; k < 9; k++) acc = fmaf(ws[oc * 9 + k], p[k], acc);
        acc = fmaxf(acc, 0.f);
        out[((b * NC + oc) * NN + gy) * NN + gx] = acc;
    }
}

// ---------------- Conv 32 -> 32, ReLU -----------------------------------------
// block 256 = 4 oc-groups x 64 threads; each thread: 8 oc x 4 px accumulators.
// Tile 32x8 output pixels. Weights resident in smem (36KB).
__global__ void conv32_kernel(const float* __restrict__ in,   // [B,32,N,N]
                              const float* __restrict__ w,    // [32,32,3,3]
                              const float* __restrict__ bias, // [32]
                              float* __restrict__ out) {      // [B,32,N,N]
    __shared__ float ws[32 * 32 * 9];     // 36864 B
    __shared__ float bs[32];
    __shared__ float tile[10][35];        // padded: conflict-free patch reads
    int tid = threadIdx.x;
    for (int i = tid; i < 9216; i += 256) ws[i] = w[i];
    if (tid < 32) bs[tid] = bias[tid];

    int tx0 = blockIdx.x * 32, ty0 = blockIdx.y * 8, b = blockIdx.z;
    int ocg = tid >> 6;          // 0..3 (uniform per warp-pair)
    int lig = tid & 63;
    int ly  = lig >> 3;          // 0..7
    int lx0 = (lig & 7) * 4;     // 0,4,...,28

    float acc[8][4];
#pragma unroll
    for (int o = 0; o < 8; o++)
#pragma unroll
        for (int q = 0; q < 4; q++) acc[o][q] = 0.f;

    const float* inb = in + b * NC * NN * NN;
    for (int c = 0; c < NC; c++) {
        __syncthreads();
        const float* ip = inb + c * NN * NN;
        for (int i = tid; i < 340; i += 256) {
            int r = i / 34, cc = i % 34;
            int gy = ty0 + r - 1, gx = tx0 + cc - 1;
            tile[r][cc] = ((unsigned)gy < (unsigned)NN && (unsigned)gx < (unsigned)NN)
                              ? ip[gy * NN + gx] : 0.f;
        }
        __syncthreads();
        const float* wc = ws + c * 9;   // + oc*288
#pragma unroll
        for (int ky = 0; ky < 3; ky++) {
#pragma unroll
            for (int kx = 0; kx < 3; kx++) {
                float p0 = tile[ly + ky][lx0 + kx + 0];
                float p1 = tile[ly + ky][lx0 + kx + 1];
                float p2 = tile[ly + ky][lx0 + kx + 2];
                float p3 = tile[ly + ky][lx0 + kx + 3];
                int wi = ky * 3 + kx;
#pragma unroll
                for (int o = 0; o < 8; o++) {
                    float wv = wc[(ocg * 8 + o) * 288 + wi];  // uniform per warp
                    acc[o][0] = fmaf(wv, p0, acc[o][0]);
                    acc[o][1] = fmaf(wv, p1, acc[o][1]);
                    acc[o][2] = fmaf(wv, p2, acc[o][2]);
                    acc[o][3] = fmaf(wv, p3, acc[o][3]);
                }
            }
        }
    }
    int gy = ty0 + ly;
#pragma unroll
    for (int o = 0; o < 8; o++) {
        int oc = ocg * 8 + o;
        float bv = bs[oc];
        float* op = out + ((b * NC + oc) * NN + gy) * NN + tx0 + lx0;
#pragma unroll
        for (int q = 0; q < 4; q++) {
            float v = acc[o][q] + bv;
            op[q] = fmaxf(v, 0.f);
        }
    }
}

// ---------------- Conv 32 -> 1 (no bias, no relu) -----------------------------
__global__ void conv4_kernel(const float* __restrict__ in,  // [B,32,N,N]
                             const float* __restrict__ w,   // [1,32,3,3]
                             float* __restrict__ out) {     // [B,N,N]
    __shared__ float ws[288];
    __shared__ float tile[10][35];
    int tid = threadIdx.x;
    for (int i = tid; i < 288; i += 256) ws[i] = w[i];   // FIXED: full 288 loads
    int tx0 = blockIdx.x * 32, ty0 = blockIdx.y * 8, b = blockIdx.z;
    int lx = tid & 31, ly = tid >> 5;
    float acc = 0.f;
    for (int c = 0; c < NC; c++) {
        __syncthreads();
        const float* ip = in + (b * NC + c) * NN * NN;
        for (int i = tid; i < 340; i += 256) {
            int r = i / 34, cc = i % 34;
            int gy = ty0 + r - 1, gx = tx0 + cc - 1;
            tile[r][cc] = ((unsigned)gy < (unsigned)NN && (unsigned)gx < (unsigned)NN)
                              ? ip[gy * NN + gx] : 0.f;
        }
        __syncthreads();
#pragma unroll
        for (int ky = 0; ky < 3; ky++)
#pragma unroll
            for (int kx = 0; kx < 3; kx++)
                acc = fmaf(ws[c * 9 + ky * 3 + kx], tile[ly + ky][lx + kx], acc);
    }
    out[b * NN * NN + (ty0 + ly) * NN + tx0 + lx] = acc;
}

// ---------------- finalize: 3 copies of X -------------------------------------
__global__ void finalize_kernel(const float* __restrict__ X, float* __restrict__ out,
                                int out_size) {
    int i = blockIdx.x * blockDim.x + threadIdx.x;
    if (i < out_size) out[i] = X[i % BNN];
}

// ---------------- host orchestration ------------------------------------------
extern "C" void kernel_launch(void* const* d_in, const int* in_sizes, int n_in,
                              void* d_out, int out_size) {
    // input order: cond, x0, sinogram, theta, theta_label, w1,b1,w2,b2,w3,b3,w4,steps
    const float* x0    = (const float*)d_in[1];
    const float* sino  = (const float*)d_in[2];
    const float* theta = (const float*)d_in[3];
    const float* w1    = (const float*)d_in[5];
    const float* b1    = (const float*)d_in[6];
    const float* w2    = (const float*)d_in[7];
    const float* b2    = (const float*)d_in[8];
    const float* w3    = (const float*)d_in[9];
    const float* b3    = (const float*)d_in[10];
    const float* w4    = (const float*)d_in[11];
    const float* steps = (const float*)d_in[12];

    float *X, *Z, *noise, *f0, *f1, *sp, *res;
    cudaGetSymbolAddress((void**)&X,     g_X);
    cudaGetSymbolAddress((void**)&Z,     g_Z);
    cudaGetSymbolAddress((void**)&noise, g_noise);
    cudaGetSymbolAddress((void**)&f0,    g_f0);
    cudaGetSymbolAddress((void**)&f1,    g_f1);
    cudaGetSymbolAddress((void**)&sp,    g_sp);
    cudaGetSymbolAddress((void**)&res,   g_res);

    const int radon_blocks = (BAD * 32 + 255) / 256;      // warp per output
    const dim3 conv_grid(NN / 32, NN / 8, NB);

    // X = x0
    copy_kernel<<<(BNN + 255) / 256, 256>>>(X, x0, BNN);

    for (int n = 0; n < NL; n++) {
        // data-consistency branch
        radon_kernel<<<radon_blocks, 256>>>(X, theta, sp);
        filter_kernel<<<NB * NA, 256>>>(sp, sino, res, /*mode=*/0);
        backproj_kernel<<<(BNN + 255) / 256, 256>>>(res, theta, X, nullptr, Z,
                                                    steps, n, /*mode=*/0);
        // denoiser branch
        conv1_kernel<<<conv_grid, 256>>>(X, w1 + n * 288, b1 + n * 32, f0);
        conv32_kernel<<<conv_grid, 256>>>(f0, w2 + n * 9216, b2 + n * 32, f1);
        conv32_kernel<<<conv_grid, 256>>>(f1, w3 + n * 9216, b3 + n * 32, f0);
        conv4_kernel<<<conv_grid, 256>>>(f0, w4 + n * 288, noise);

        radon_kernel<<<radon_blocks, 256>>>(noise, theta, sp);
        filter_kernel<<<NB * NA, 256>>>(sp, nullptr, res, /*mode=*/1);
        backproj_kernel<<<(BNN + 255) / 256, 256>>>(res, theta, Z, noise, X,
                                                    steps, n, /*mode=*/1);
    }

    finalize_kernel<<<(out_size + 255) / 256, 256>>>(X, (float*)d_out, out_size);
}

// round 13
// speedup vs baseline: 1.1099x; 1.1099x over previous
#include <cuda_runtime.h>
#include <math.h>

// Problem constants
#define NN 512          // image size
#define NA 30           // angles
#define ND 729          // detectors
#define NL 3            // layers
#define NB 2            // batch
#define NC 32           // hidden channels

#define PI_F 3.14159265358979323846f

static const int BNN = NB * NN * NN;           // 524288
static const int BAD = NB * NA * ND;           // 43740
static const int NODD = 364;                   // number of odd taps 1..727

typedef unsigned long long ull;

// packed fp32x2 helpers (Blackwell packed-FP32; ptxas never auto-emits these)
#define FMA_F32X2(d, a, b, c) \
    asm("fma.rn.f32x2 %0, %1, %2, %3;" : "=l"(d) : "l"(a), "l"(b), "l"(c))
#define PACK_F32X2(out, lo, hi) \
    asm("mov.b64 %0, {%1, %2};" : "=l"(out) : "f"(lo), "f"(hi))
#define UNPACK_F32X2(lo, hi, in) \
    asm("mov.b64 {%0, %1}, %2;" : "=f"(lo), "=f"(hi) : "l"(in))

// ---------------- scratch (device globals; no allocation allowed) -----------
__device__ float g_X[NB * NN * NN];
__device__ float g_Z[NB * NN * NN];
__device__ float g_noise[NB * NN * NN];
__device__ float g_f0[NB * NC * NN * NN];
__device__ float g_f1[NB * NC * NN * NN];
__device__ float g_sp[NB * NA * ND];
__device__ float g_res[NB * NA * ND];

// ---------------- trivial copy ----------------------------------------------
__global__ void copy_kernel(float* __restrict__ dst, const float* __restrict__ src, int n) {
    int i = blockIdx.x * blockDim.x + threadIdx.x;
    if (i < n) dst[i] = src[i];
}

// ---------------- Radon forward ----------------------------------------------
__global__ void radon_kernel(const float* __restrict__ img,
                             const float* __restrict__ theta,
                             float* __restrict__ out) {
    int gw   = (int)((blockIdx.x * blockDim.x + threadIdx.x) >> 5);
    int lane = threadIdx.x & 31;
    if (gw >= BAD) return;
    int b   = gw / (NA * ND);
    int rem = gw - b * NA * ND;
    int a   = rem / ND;
    int s   = rem - a * ND;

    float th = theta[a];
    float cs = cosf(th), sn = sinf(th);
    float sv = (float)s - 364.0f;
    float base_r = sv * sn + 255.5f;
    float base_c = sv * cs + 255.5f;
    const float* im = img + b * NN * NN;

    float acc = 0.0f;
    for (int t = lane; t < ND; t += 32) {
        float tv = (float)t - 364.0f;
        float r = base_r + tv * cs;
        float c = base_c - tv * sn;
        float rf = floorf(r), cf = floorf(c);
        int r0 = (int)rf, c0 = (int)cf;
        float wr = r - rf, wc = c - cf;
        float v00 = 0.f, v01 = 0.f, v10 = 0.f, v11 = 0.f;
        bool r0k = (unsigned)r0 < (unsigned)NN;
        bool r1k = (unsigned)(r0 + 1) < (unsigned)NN;
        bool c0k = (unsigned)c0 < (unsigned)NN;
        bool c1k = (unsigned)(c0 + 1) < (unsigned)NN;
        if (r0k) {
            const float* rp = im + r0 * NN;
            if (c0k) v00 = rp[c0];
            if (c1k) v01 = rp[c0 + 1];
        }
        if (r1k) {
            const float* rp = im + (r0 + 1) * NN;
            if (c0k) v10 = rp[c0];
            if (c1k) v11 = rp[c0 + 1];
        }
        acc += (1.f - wr) * ((1.f - wc) * v00 + wc * v01)
             +        wr  * ((1.f - wc) * v10 + wc * v11);
    }
#pragma unroll
    for (int o = 16; o; o >>= 1) acc += __shfl_xor_sync(0xffffffffu, acc, o);
    if (lane == 0) out[gw] = acc;
}

// ---------------- Ramp filter (analytic time-domain equivalent) --------------
// grid (NB*NA, 3): blockIdx.y splits the m dimension for occupancy.
__global__ void filter_kernel(const float* __restrict__ sp,
                              const float* __restrict__ sino,
                              float* __restrict__ out, int mode) {
    __shared__ float row[ND];
    __shared__ float coef[NODD];
    int ba = blockIdx.x;                 // b*NA + a
    const float* r = sp + ba * ND;
    for (int i = threadIdx.x; i < ND; i += blockDim.x) row[i] = r[i];
    for (int i = threadIdx.x; i < NODD; i += blockDim.x) {
        float d = 2.0f * (float)i + 1.0f;
        coef[i] = -2.0f / (PI_F * PI_F * d * d);
    }
    __syncthreads();
    const float scale = PI_F / (2.0f * (float)NA);
    int m = blockIdx.y * blockDim.x + threadIdx.x;
    if (m >= ND) return;
    float g = 0.5f * row[m];
    for (int i = 0; i < NODD; i++) {
        int d = 2 * i + 1;
        float sum = 0.f;
        int lo = m - d; if (lo >= 0) sum += row[lo];
        int hi = m + d; if (hi < ND) sum += row[hi];
        g = fmaf(coef[i], sum, g);
    }
    float filtered = g * scale;
    out[ba * ND + m] = (mode == 0) ? (sino[ba * ND + m] - filtered) : filtered;
}

// ---------------- Backprojection (fused epilogue) -----------------------------
__global__ void backproj_kernel(const float* __restrict__ sino,
                                const float* __restrict__ theta,
                                const float* __restrict__ base,
                                const float* __restrict__ addl,
                                float* __restrict__ out,
                                const float* __restrict__ steps, int layer,
                                int mode) {
    __shared__ float cs_s[NA], sn_s[NA];
    if (threadIdx.x < NA) {
        float th = theta[threadIdx.x];
        cs_s[threadIdx.x] = cosf(th);
        sn_s[threadIdx.x] = sinf(th);
    }
    __syncthreads();
    int p = blockIdx.x * blockDim.x + threadIdx.x;
    if (p >= BNN) return;
    int b  = p / (NN * NN);
    int ij = p - b * NN * NN;
    int i  = ij / NN, j = ij - i * NN;
    float xi = (float)i - 255.5f;
    float xj = (float)j - 255.5f;
    const float* srow = sino + b * NA * ND;
    float acc = 0.0f;
#pragma unroll 5
    for (int a = 0; a < NA; a++) {
        float idx = cs_s[a] * xj + sn_s[a] * xi + 364.0f;
        float lof = floorf(idx);
        int lo = (int)lof;
        float w = idx - lof;
        float v = 0.f;
        if ((unsigned)lo < (unsigned)ND)       v += srow[a * ND + lo] * (1.0f - w);
        if ((unsigned)(lo + 1) < (unsigned)ND) v += srow[a * ND + lo + 1] * w;
        acc += v;
    }
    float step = steps[layer];
    float r;
    if (mode == 0) r = base[p] + step * acc;
    else           r = base[p] + addl[p] - step * acc;
    out[p] = r;
}

// ---------------- Conv 1 -> 32, ReLU -----------------------------------------
__global__ void conv1_kernel(const float* __restrict__ in,   // [B,N,N]
                             const float* __restrict__ w,    // [32,1,3,3]
                             const float* __restrict__ bias, // [32]
                             float* __restrict__ out) {      // [B,32,N,N]
    __shared__ float ws[32 * 9];
    __shared__ float bs[32];
    __shared__ float tile[10][35];
    int tid = threadIdx.x;
    for (int i = tid; i < 288; i += 256) ws[i] = w[i];
    if (tid < 32)  bs[tid] = bias[tid];
    int tx0 = blockIdx.x * 32, ty0 = blockIdx.y * 8, b = blockIdx.z;
    const float* ip = in + b * NN * NN;
    for (int i = tid; i < 340; i += 256) {
        int r = i / 34, c = i % 34;
        int gy = ty0 + r - 1, gx = tx0 + c - 1;
        tile[r][c] = ((unsigned)gy < (unsigned)NN && (unsigned)gx < (unsigned)NN)
                         ? ip[gy * NN + gx] : 0.f;
    }
    __syncthreads();
    int lx = tid & 31, ly = tid >> 5;
    float p[9];
#pragma unroll
    for (int ky = 0; ky < 3; ky++)
#pragma unroll
        for (int kx = 0; kx < 3; kx++) p[ky * 3 + kx] = tile[ly + ky][lx + kx];
    int gy = ty0 + ly, gx = tx0 + lx;
#pragma unroll
    for (int oc = 0; oc < 32; oc++) {
        float acc = bs[oc];
#pragma unroll
        for (int k = 0; k < 9; k++) acc = fmaf(ws[oc * 9 + k], p[k], acc);
        acc = fmaxf(acc, 0.f);
        out[((b * NC + oc) * NN + gy) * NN + gx] = acc;
    }
}

// ---------------- Conv 32 -> 32, ReLU  (f32x2 packed, all channels resident) --
// Dynamic smem layout (floats): ws[9216] | tiles[32][10][35] | bs[32]  = 81792 B
// 256 threads = 8 oc-groups(4 oc) x 32 lanes; per thread 4 oc x 8 px (4 f32x2).
__global__ void __launch_bounds__(256, 2)
conv32_kernel(const float* __restrict__ in,   // [B,32,N,N]
              const float* __restrict__ w,    // [32,32,3,3]
              const float* __restrict__ bias, // [32]
              float* __restrict__ out) {      // [B,32,N,N]
    extern __shared__ float sm[];
    float* ws    = sm;                         // 9216
    float* tiles = sm + 9216;                  // 32 * 350
    float* bs    = sm + 9216 + 32 * 350;       // 32
    int tid = threadIdx.x;

    for (int i = tid; i < 9216; i += 256) ws[i] = w[i];
    if (tid < 32) bs[tid] = bias[tid];

    int tx0 = blockIdx.x * 32, ty0 = blockIdx.y * 8, b = blockIdx.z;
    const float* inb = in + b * NC * NN * NN;
    // load all 32 input-channel halo tiles (10 x 34 used, pitch 35)
    for (int i = tid; i < 32 * 340; i += 256) {
        int c   = i / 340;
        int rem = i - c * 340;
        int r   = rem / 34;
        int cc  = rem - r * 34;
        int gy = ty0 + r - 1, gx = tx0 + cc - 1;
        tiles[c * 350 + r * 35 + cc] =
            ((unsigned)gy < (unsigned)NN && (unsigned)gx < (unsigned)NN)
                ? inb[c * NN * NN + gy * NN + gx] : 0.f;
    }
    __syncthreads();

    int g    = tid >> 5;           // oc group 0..7 -> oc = g*4 .. g*4+3
    int lane = tid & 31;
    int ly   = lane >> 2;          // 0..7
    int lx0  = (lane & 3) * 8;     // 0,8,16,24

    ull acc[4][4];
#pragma unroll
    for (int o = 0; o < 4; o++)
#pragma unroll
        for (int q = 0; q < 4; q++) acc[o][q] = 0ULL;   // (0.f, 0.f)

    for (int c = 0; c < NC; c++) {
        const float* tl = tiles + c * 350;
        const float* wc = ws + c * 9 + g * 4 * 288;     // + o*288 + (ky*3+kx)
#pragma unroll
        for (int ky = 0; ky < 3; ky++) {
            const float* rowp = tl + (ly + ky) * 35 + lx0;
            float p[10];
#pragma unroll
            for (int k = 0; k < 10; k++) p[k] = rowp[k];
            ull pr[9];
#pragma unroll
            for (int k = 0; k < 9; k++) PACK_F32X2(pr[k], p[k], p[k + 1]);
#pragma unroll
            for (int kx = 0; kx < 3; kx++) {
#pragma unroll
                for (int o = 0; o < 4; o++) {
                    float wv = wc[o * 288 + ky * 3 + kx];   // warp-uniform LDS
                    ull wp; PACK_F32X2(wp, wv, wv);
                    FMA_F32X2(acc[o][0], wp, pr[kx + 0], acc[o][0]);
                    FMA_F32X2(acc[o][1], wp, pr[kx + 2], acc[o][1]);
                    FMA_F32X2(acc[o][2], wp, pr[kx + 4], acc[o][2]);
                    FMA_F32X2(acc[o][3], wp, pr[kx + 6], acc[o][3]);
                }
            }
        }
    }

    int gy = ty0 + ly;
#pragma unroll
    for (int o = 0; o < 4; o++) {
        int oc = g * 4 + o;
        float bv = bs[oc];
        float* op = out + ((b * NC + oc) * NN + gy) * NN + tx0 + lx0;
#pragma unroll
        for (int q = 0; q < 4; q++) {
            float lo, hi;
            UNPACK_F32X2(lo, hi, acc[o][q]);
            op[2 * q + 0] = fmaxf(lo + bv, 0.f);
            op[2 * q + 1] = fmaxf(hi + bv, 0.f);
        }
    }
}

// ---------------- Conv 32 -> 1 (all channels resident, single sync) ----------
__global__ void conv4_kernel(const float* __restrict__ in,  // [B,32,N,N]
                             const float* __restrict__ w,   // [1,32,3,3]
                             float* __restrict__ out) {     // [B,N,N]
    __shared__ float ws[288];
    __shared__ float tiles[32 * 350];
    int tid = threadIdx.x;
    for (int i = tid; i < 288; i += 256) ws[i] = w[i];
    int tx0 = blockIdx.x * 32, ty0 = blockIdx.y * 8, b = blockIdx.z;
    const float* inb = in + b * NC * NN * NN;
    for (int i = tid; i < 32 * 340; i += 256) {
        int c   = i / 340;
        int rem = i - c * 340;
        int r   = rem / 34;
        int cc  = rem - r * 34;
        int gy = ty0 + r - 1, gx = tx0 + cc - 1;
        tiles[c * 350 + r * 35 + cc] =
            ((unsigned)gy < (unsigned)NN && (unsigned)gx < (unsigned)NN)
                ? inb[c * NN * NN + gy * NN + gx] : 0.f;
    }
    __syncthreads();
    int lx = tid & 31, ly = tid >> 5;
    float acc = 0.f;
    for (int c = 0; c < NC; c++) {
        const float* tl = tiles + c * 350;
#pragma unroll
        for (int ky = 0; ky < 3; ky++)
#pragma unroll
            for (int kx = 0; kx < 3; kx++)
                acc = fmaf(ws[c * 9 + ky * 3 + kx], tl[(ly + ky) * 35 + lx + kx], acc);
    }
    out[b * NN * NN + (ty0 + ly) * NN + tx0 + lx] = acc;
}

// ---------------- finalize: 3 copies of X -------------------------------------
__global__ void finalize_kernel(const float* __restrict__ X, float* __restrict__ out,
                                int out_size) {
    int i = blockIdx.x * blockDim.x + threadIdx.x;
    if (i < out_size) out[i] = X[i % BNN];
}

// ---------------- host orchestration ------------------------------------------
extern "C" void kernel_launch(void* const* d_in, const int* in_sizes, int n_in,
                              void* d_out, int out_size) {
    // input order: cond, x0, sinogram, theta, theta_label, w1,b1,w2,b2,w3,b3,w4,steps
    const float* x0    = (const float*)d_in[1];
    const float* sino  = (const float*)d_in[2];
    const float* theta = (const float*)d_in[3];
    const float* w1    = (const float*)d_in[5];
    const float* b1    = (const float*)d_in[6];
    const float* w2    = (const float*)d_in[7];
    const float* b2    = (const float*)d_in[8];
    const float* w3    = (const float*)d_in[9];
    const float* b3    = (const float*)d_in[10];
    const float* w4    = (const float*)d_in[11];
    const float* steps = (const float*)d_in[12];

    float *X, *Z, *noise, *f0, *f1, *sp, *res;
    cudaGetSymbolAddress((void**)&X,     g_X);
    cudaGetSymbolAddress((void**)&Z,     g_Z);
    cudaGetSymbolAddress((void**)&noise, g_noise);
    cudaGetSymbolAddress((void**)&f0,    g_f0);
    cudaGetSymbolAddress((void**)&f1,    g_f1);
    cudaGetSymbolAddress((void**)&sp,    g_sp);
    cudaGetSymbolAddress((void**)&res,   g_res);

    const int conv32_smem = (9216 + 32 * 350 + 32) * (int)sizeof(float); // 81792 B
    cudaFuncSetAttribute(conv32_kernel,
                         cudaFuncAttributeMaxDynamicSharedMemorySize, conv32_smem);

    const int radon_blocks = (BAD * 32 + 255) / 256;      // warp per output
    const dim3 conv_grid(NN / 32, NN / 8, NB);
    const dim3 filt_grid(NB * NA, 3);

    // X = x0
    copy_kernel<<<(BNN + 255) / 256, 256>>>(X, x0, BNN);

    for (int n = 0; n < NL; n++) {
        // data-consistency branch
        radon_kernel<<<radon_blocks, 256>>>(X, theta, sp);
        filter_kernel<<<filt_grid, 256>>>(sp, sino, res, /*mode=*/0);
        backproj_kernel<<<(BNN + 255) / 256, 256>>>(res, theta, X, nullptr, Z,
                                                    steps, n, /*mode=*/0);
        // denoiser branch
        conv1_kernel<<<conv_grid, 256>>>(X, w1 + n * 288, b1 + n * 32, f0);
        conv32_kernel<<<conv_grid, 256, conv32_smem>>>(f0, w2 + n * 9216, b2 + n * 32, f1);
        conv32_kernel<<<conv_grid, 256, conv32_smem>>>(f1, w3 + n * 9216, b3 + n * 32, f0);
        conv4_kernel<<<conv_grid, 256>>>(f0, w4 + n * 288, noise);

        radon_kernel<<<radon_blocks, 256>>>(noise, theta, sp);
        filter_kernel<<<filt_grid, 256>>>(sp, nullptr, res, /*mode=*/1);
        backproj_kernel<<<(BNN + 255) / 256, 256>>>(res, theta, Z, noise, X,
                                                    steps, n, /*mode=*/1);
    }

    finalize_kernel<<<(out_size + 255) / 256, 256>>>(X, (float*)d_out, out_size);
}